// round 16
// baseline (speedup 1.0000x reference)
#include <cuda_runtime.h>
#include <cuda_bf16.h>
#include <cuda_fp16.h>
#include <cuda_pipeline.h>
#include <mma.h>
#include <cstdint>

using namespace nvcuda;

#define NN     50000
#define NPAD   50048    // = 782*64 = 391*128
#define IN_F   256
#define H_F    128
#define OUT_F  64
#define EMAX   800000

// ---------------------------------------------------------------------------
// Static device scratch
// ---------------------------------------------------------------------------
__device__ __align__(16) __half g_th[(size_t)NPAD * H_F];    // layer-1 GEMM out (fp16)
__device__ __align__(16) __half g_t2h[(size_t)NPAD * OUT_F]; // layer-2 GEMM out (fp16)
__device__ __align__(16) __nv_bfloat16 ga_hi[(size_t)NPAD * H_F];
__device__ __align__(16) __nv_bfloat16 ga_lo[(size_t)NPAD * H_F];
__device__ __align__(16) __nv_bfloat16 gw1_hi[IN_F * H_F];
__device__ __align__(16) __nv_bfloat16 gw1_lo[IN_F * H_F];
__device__ __align__(16) __nv_bfloat16 gw2_hi[H_F * OUT_F];
__device__ __align__(16) __nv_bfloat16 gw2_lo[H_F * OUT_F];
__device__ float g_dinv[NN];
__device__ int   g_cnt[NN];      // invariant: all-zero at entry of every call
__device__ int   g_off[NN + 1];
__device__ int   g_col[EMAX];
__device__ int   g_bsum[256];
__device__ int   g_is64;

__device__ __forceinline__ void split_bf16(float v, __nv_bfloat16& h, __nv_bfloat16& l) {
    h = __float2bfloat16_rn(v);
    l = __float2bfloat16_rn(v - __bfloat162float(h));
}

// ---------------------------------------------------------------------------
// Weight pre-split (x split is fused into GEMM1)
// ---------------------------------------------------------------------------
__global__ void wsplit_kernel(const float* __restrict__ W1, const float* __restrict__ W2) {
    int i = blockIdx.x * blockDim.x + threadIdx.x;                 // quad index
    const int Q1 = IN_F * H_F / 4;
    const int Q2 = H_F * OUT_F / 4;
    if (i >= Q1 + Q2) return;
    const float4 v = (i < Q1) ? reinterpret_cast<const float4*>(W1)[i]
                              : reinterpret_cast<const float4*>(W2)[i - Q1];
    __nv_bfloat16 h0, l0, h1, l1, h2, l2, h3, l3;
    split_bf16(v.x, h0, l0); split_bf16(v.y, h1, l1);
    split_bf16(v.z, h2, l2); split_bf16(v.w, h3, l3);
    __nv_bfloat162* ph;
    __nv_bfloat162* pl;
    if (i < Q1) {
        ph = reinterpret_cast<__nv_bfloat162*>(gw1_hi) + 2 * i;
        pl = reinterpret_cast<__nv_bfloat162*>(gw1_lo) + 2 * i;
    } else {
        ph = reinterpret_cast<__nv_bfloat162*>(gw2_hi) + 2 * (i - Q1);
        pl = reinterpret_cast<__nv_bfloat162*>(gw2_lo) + 2 * (i - Q1);
    }
    ph[0] = __nv_bfloat162(h0, h1); ph[1] = __nv_bfloat162(h2, h3);
    pl[0] = __nv_bfloat162(l0, l1); pl[1] = __nv_bfloat162(l2, l3);
}

// ---------------------------------------------------------------------------
// Edge width autodetect
// ---------------------------------------------------------------------------
__global__ void detect_kernel(const int* __restrict__ ei32) {
    if (threadIdx.x == 0 && blockIdx.x == 0) {
        int allzero = 1;
        for (int i = 0; i < 64; i++)
            if (ei32[2 * i + 1] != 0) { allzero = 0; break; }
        g_is64 = allzero;
    }
}
__device__ __forceinline__ int edge_src(const int* ei, int E, int e) {
    return g_is64 ? ei[2 * (size_t)e] : ei[(size_t)e];
}
__device__ __forceinline__ int edge_dst(const int* ei, int E, int e) {
    return g_is64 ? ei[2 * ((size_t)E + e)] : ei[(size_t)E + e];
}

// ---------------------------------------------------------------------------
// CSR build. g_cnt is all-zero on entry (restored by scatter's decrement).
// ---------------------------------------------------------------------------
__global__ void hist_kernel(const int* __restrict__ ei, int E) {
    int e = blockIdx.x * blockDim.x + threadIdx.x;
    if (e >= E) return;
    int d = edge_dst(ei, E, e);
    if ((unsigned)d < (unsigned)NN) atomicAdd(&g_cnt[d], 1);
}
__global__ void scan_local_kernel(int n) {
    __shared__ int sh[256];
    const int tid = threadIdx.x;
    const int i = blockIdx.x * 256 + tid;
    int v = (i < n) ? g_cnt[i] : 0;
    sh[tid] = v;
    __syncthreads();
#pragma unroll
    for (int off = 1; off < 256; off <<= 1) {
        int u = (tid >= off) ? sh[tid - off] : 0;
        __syncthreads();
        sh[tid] += u;
        __syncthreads();
    }
    if (i < n) g_off[i] = sh[tid] - v;
    if (tid == 255) g_bsum[blockIdx.x] = sh[255];
}
__global__ void scan_bsum_kernel(int nb) {
    __shared__ int sh[256];
    const int tid = threadIdx.x;
    int v = (tid < nb) ? g_bsum[tid] : 0;
    sh[tid] = v;
    __syncthreads();
#pragma unroll
    for (int off = 1; off < 256; off <<= 1) {
        int u = (tid >= off) ? sh[tid - off] : 0;
        __syncthreads();
        sh[tid] += u;
        __syncthreads();
    }
    if (tid < nb) g_bsum[tid] = sh[tid] - v;
}
__global__ void scan_apply_kernel(int n) {
    int i = blockIdx.x * 256 + threadIdx.x;
    if (i >= n) return;
    int base = g_bsum[blockIdx.x];
    int c = g_cnt[i];                 // NOT reset here; scatter decrements to 0
    int o = g_off[i] + base;
    g_off[i] = o;
    g_dinv[i] = rsqrtf((float)(c + 1));
    if (i == n - 1) g_off[n] = o + c;
}
__global__ void scatter_kernel(const int* __restrict__ ei, int E) {
    int e = blockIdx.x * blockDim.x + threadIdx.x;
    if (e >= E) return;
    int s = edge_src(ei, E, e);
    int d = edge_dst(ei, E, e);
    if ((unsigned)d >= (unsigned)NN) return;
    int r = atomicAdd(&g_cnt[d], -1);            // restores cnt to 0 for next call
    if ((unsigned)s < (unsigned)NN) g_col[g_off[d] + r - 1] = s;
}

// ---------------------------------------------------------------------------
// Aggregation (gather, fp16 rows, f32 accumulate).
// agg1: warp per node, 4 halves/lane (8B), edge-unrolled x2.
// agg2: half-warp per node, 4 halves/lane.
// ---------------------------------------------------------------------------
__device__ __forceinline__ void h4_fma(uint2 raw, float w, float4& acc) {
    __half2 a = *reinterpret_cast<__half2*>(&raw.x);
    __half2 b = *reinterpret_cast<__half2*>(&raw.y);
    float2 f0 = __half22float2(a), f1 = __half22float2(b);
    acc.x = fmaf(f0.x, w, acc.x);
    acc.y = fmaf(f0.y, w, acc.y);
    acc.z = fmaf(f1.x, w, acc.z);
    acc.w = fmaf(f1.y, w, acc.w);
}

__global__ void agg1_kernel(const float* __restrict__ b1, int n) {
    int gw   = (blockIdx.x * blockDim.x + threadIdx.x) >> 5;
    int lane = threadIdx.x & 31;
    if (gw >= n) return;

    float wd = g_dinv[gw];
    float ws = wd * wd;
    float4 acc = make_float4(0.f, 0.f, 0.f, 0.f);
    h4_fma(*reinterpret_cast<const uint2*>(g_th + (size_t)gw * 128 + lane * 4), ws, acc);

    int beg = g_off[gw], end = g_off[gw + 1];
    int e = beg;
    for (; e + 1 < end; e += 2) {
        int s0 = g_col[e], s1 = g_col[e + 1];
        float w0 = g_dinv[s0] * wd, w1 = g_dinv[s1] * wd;
        uint2 r0 = *reinterpret_cast<const uint2*>(g_th + (size_t)s0 * 128 + lane * 4);
        uint2 r1 = *reinterpret_cast<const uint2*>(g_th + (size_t)s1 * 128 + lane * 4);
        h4_fma(r0, w0, acc);
        h4_fma(r1, w1, acc);
    }
    if (e < end) {
        int s = g_col[e];
        float w = g_dinv[s] * wd;
        h4_fma(*reinterpret_cast<const uint2*>(g_th + (size_t)s * 128 + lane * 4), w, acc);
    }
    float4 bb = reinterpret_cast<const float4*>(b1)[lane];
    acc.x = fmaxf(acc.x + bb.x, 0.f);
    acc.y = fmaxf(acc.y + bb.y, 0.f);
    acc.z = fmaxf(acc.z + bb.z, 0.f);
    acc.w = fmaxf(acc.w + bb.w, 0.f);

    __nv_bfloat16 h0, l0, h1, l1, h2, l2, h3, l3;
    split_bf16(acc.x, h0, l0); split_bf16(acc.y, h1, l1);
    split_bf16(acc.z, h2, l2); split_bf16(acc.w, h3, l3);
    size_t o = (size_t)gw * (H_F / 2) + lane * 2;   // bf16x2 index
    reinterpret_cast<__nv_bfloat162*>(ga_hi)[o]     = __nv_bfloat162(h0, h1);
    reinterpret_cast<__nv_bfloat162*>(ga_hi)[o + 1] = __nv_bfloat162(h2, h3);
    reinterpret_cast<__nv_bfloat162*>(ga_lo)[o]     = __nv_bfloat162(l0, l1);
    reinterpret_cast<__nv_bfloat162*>(ga_lo)[o + 1] = __nv_bfloat162(l2, l3);
}

__global__ void agg2_kernel(const float* __restrict__ b2, float* __restrict__ out, int n) {
    int gh = (blockIdx.x * blockDim.x + threadIdx.x) >> 4;  // half-warp id = node
    int hl = threadIdx.x & 15;
    if (gh >= n) return;

    float wd = g_dinv[gh];
    float ws = wd * wd;
    float4 acc = make_float4(0.f, 0.f, 0.f, 0.f);
    h4_fma(*reinterpret_cast<const uint2*>(g_t2h + (size_t)gh * 64 + hl * 4), ws, acc);

    int beg = g_off[gh], end = g_off[gh + 1];
    int e = beg;
    for (; e + 1 < end; e += 2) {
        int s0 = g_col[e], s1 = g_col[e + 1];
        float w0 = g_dinv[s0] * wd, w1 = g_dinv[s1] * wd;
        uint2 r0 = *reinterpret_cast<const uint2*>(g_t2h + (size_t)s0 * 64 + hl * 4);
        uint2 r1 = *reinterpret_cast<const uint2*>(g_t2h + (size_t)s1 * 64 + hl * 4);
        h4_fma(r0, w0, acc);
        h4_fma(r1, w1, acc);
    }
    if (e < end) {
        int s = g_col[e];
        float w = g_dinv[s] * wd;
        h4_fma(*reinterpret_cast<const uint2*>(g_t2h + (size_t)s * 64 + hl * 4), w, acc);
    }
    float4 bb = reinterpret_cast<const float4*>(b2)[hl];
    acc.x += bb.x; acc.y += bb.y; acc.z += bb.z; acc.w += bb.w;
    reinterpret_cast<float4*>(out)[(size_t)gh * 16 + hl] = acc;
}

// ---------------------------------------------------------------------------
// Shared epilogue helper: f32 tile in smem -> fp16 global (8 halves/chunk)
// ---------------------------------------------------------------------------
template<int ROWS, int COLS>
__device__ __forceinline__ void epilogue_f32_to_h(const float* cst, __half* dst,
                                                  int row0, int tid) {
#pragma unroll
    for (int idx = tid; idx < ROWS * (COLS / 8); idx += 256) {
        int r = idx / (COLS / 8), q = idx % (COLS / 8);
        const float* p = cst + r * COLS + q * 8;
        __half2 h[4];
        h[0] = __floats2half2_rn(p[0], p[1]);
        h[1] = __floats2half2_rn(p[2], p[3]);
        h[2] = __floats2half2_rn(p[4], p[5]);
        h[3] = __floats2half2_rn(p[6], p[7]);
        *reinterpret_cast<uint4*>(dst + (size_t)(row0 + r) * COLS + q * 8) =
            *reinterpret_cast<uint4*>(h);
    }
}

// ---------------------------------------------------------------------------
// GEMM1 with FUSED x split: cp.async raw f32 A tiles, convert to bf16 hi/lo
// in smem. Output written as fp16 (g_th). BM=64, BN=128, BK=32, 256 threads.
// ---------------------------------------------------------------------------
__global__ void __launch_bounds__(256)
gemm1_fused_kernel(const float* __restrict__ x) {
    constexpr int BM = 64, BN = 128, BK = 32, K = IN_F, N = H_F;
    constexpr int BKP = 48;
    constexpr int BNP = 136;
    constexpr int T = K / BK;
    constexpr int KK = BK / 16;
    constexpr int AM = 2, AN = 2, WARPS_N = 4;
    constexpr int AF_STAGE = BM * BK * 4;            // 8192 B
    constexpr int OFF_AF  = 0;
    constexpr int OFF_AHI = 2 * AF_STAGE;
    constexpr int OFF_ALO = OFF_AHI + BM * BKP * 2;
    constexpr int OFF_B   = OFF_ALO + BM * BKP * 2;  // 28672
    constexpr int SB = BK * BNP * 2;

    extern __shared__ __align__(32) char smem_raw[];
    float* af = reinterpret_cast<float*>(smem_raw + OFF_AF);
    __nv_bfloat16* ahi_s = reinterpret_cast<__nv_bfloat16*>(smem_raw + OFF_AHI);
    __nv_bfloat16* alo_s = reinterpret_cast<__nv_bfloat16*>(smem_raw + OFF_ALO);

    const int tid = threadIdx.x;
    const int wid = tid >> 5;
    const int wm = wid / WARPS_N;
    const int wn = wid % WARPS_N;
    const int row0 = blockIdx.x * BM;

    auto bs_hi = [&](int s) { return reinterpret_cast<__nv_bfloat16*>(smem_raw + OFF_B + s * 2 * SB); };
    auto bs_lo = [&](int s) { return reinterpret_cast<__nv_bfloat16*>(smem_raw + OFF_B + s * 2 * SB + SB); };

    auto copy_stage = [&](int s, int t) {
        const int kbase = t * BK;
#pragma unroll
        for (int idx = tid; idx < BM * (BK / 4); idx += 256) {
            int r = idx >> 3, q = idx & 7;
            int gr = row0 + r; if (gr >= NN) gr = NN - 1;   // clamp; zeroed in convert
            __pipeline_memcpy_async(af + s * (AF_STAGE / 4) + idx * 4,
                                    x + (size_t)gr * K + kbase + q * 4, 16);
        }
#pragma unroll
        for (int idx = tid; idx < BK * (BN / 8); idx += 256) {
            int r = idx / (BN / 8), q = idx % (BN / 8);
            size_t go = (size_t)(kbase + r) * N + q * 8;
            int so = r * BNP + q * 8;
            __pipeline_memcpy_async(bs_hi(s) + so, gw1_hi + go, 16);
            __pipeline_memcpy_async(bs_lo(s) + so, gw1_lo + go, 16);
        }
    };

    wmma::fragment<wmma::accumulator, 16, 16, 16, float> acc[AM][AN];
#pragma unroll
    for (int m = 0; m < AM; m++)
#pragma unroll
        for (int n = 0; n < AN; n++) wmma::fill_fragment(acc[m][n], 0.f);

    copy_stage(0, 0);
    __pipeline_commit();

    for (int t = 0; t < T; t++) {
        __pipeline_wait_prior(0);
        __syncthreads();
        if (t + 1 < T) {
            copy_stage((t + 1) & 1, t + 1);
            __pipeline_commit();
        }
        const int s = t & 1;
#pragma unroll
        for (int idx = tid; idx < BM * (BK / 4); idx += 256) {
            int r = idx >> 3, c = (idx & 7) * 4;
            float4 v = *reinterpret_cast<const float4*>(af + s * (AF_STAGE / 4) + idx * 4);
            if (row0 + r >= NN) v = make_float4(0.f, 0.f, 0.f, 0.f);
            __nv_bfloat16 h0, l0, h1, l1, h2, l2, h3, l3;
            split_bf16(v.x, h0, l0); split_bf16(v.y, h1, l1);
            split_bf16(v.z, h2, l2); split_bf16(v.w, h3, l3);
            int o = r * BKP + c;
            *reinterpret_cast<__nv_bfloat162*>(&ahi_s[o])     = __nv_bfloat162(h0, h1);
            *reinterpret_cast<__nv_bfloat162*>(&ahi_s[o + 2]) = __nv_bfloat162(h2, h3);
            *reinterpret_cast<__nv_bfloat162*>(&alo_s[o])     = __nv_bfloat162(l0, l1);
            *reinterpret_cast<__nv_bfloat162*>(&alo_s[o + 2]) = __nv_bfloat162(l2, l3);
        }
        __syncthreads();
#pragma unroll
        for (int kk = 0; kk < KK; kk++) {
            wmma::fragment<wmma::matrix_a, 16, 16, 16, __nv_bfloat16, wmma::row_major> ahi[AM], alo[AM];
#pragma unroll
            for (int m = 0; m < AM; m++) {
                int o = (wm * 32 + m * 16) * BKP + kk * 16;
                wmma::load_matrix_sync(ahi[m], ahi_s + o, BKP);
                wmma::load_matrix_sync(alo[m], alo_s + o, BKP);
            }
#pragma unroll
            for (int n = 0; n < AN; n++) {
                wmma::fragment<wmma::matrix_b, 16, 16, 16, __nv_bfloat16, wmma::row_major> bhi, blo;
                int o = (kk * 16) * BNP + wn * 32 + n * 16;
                wmma::load_matrix_sync(bhi, bs_hi(s) + o, BNP);
                wmma::load_matrix_sync(blo, bs_lo(s) + o, BNP);
#pragma unroll
                for (int m = 0; m < AM; m++) {
                    wmma::mma_sync(acc[m][n], alo[m], bhi, acc[m][n]);
                    wmma::mma_sync(acc[m][n], ahi[m], blo, acc[m][n]);
                    wmma::mma_sync(acc[m][n], ahi[m], bhi, acc[m][n]);
                }
            }
        }
    }

    // Epilogue: stage f32 tile in smem (reuse), convert to fp16, write g_th
    __syncthreads();
    float* cst = reinterpret_cast<float*>(smem_raw);   // 64*128*4 = 32KB
#pragma unroll
    for (int m = 0; m < AM; m++)
#pragma unroll
        for (int n = 0; n < AN; n++)
            wmma::store_matrix_sync(cst + (wm * 32 + m * 16) * BN + wn * 32 + n * 16,
                                    acc[m][n], BN, wmma::mem_row_major);
    __syncthreads();
    epilogue_f32_to_h<BM, BN>(cst, g_th, row0, tid);
}

// ---------------------------------------------------------------------------
// GEMM2: pre-split bf16 A (ga), fp16 output (g_t2h).
// BM=128, BN=64, BK=32, 256 threads.
// ---------------------------------------------------------------------------
__global__ void __launch_bounds__(256)
gemm2_kernel() {
    constexpr int BM = 128, BN = 64, BK = 32, K = H_F, N = OUT_F;
    constexpr int BKP = 48;
    constexpr int BNP = 80;
    constexpr int WARPS_N = 2;
    constexpr int AM = 2, AN = 2;
    constexpr int KK = 2;
    constexpr int T = K / BK;
    constexpr int SA = BM * BKP * 2;
    constexpr int SB = BK * BNP * 2;
    constexpr int STAGE = 2 * SA + 2 * SB;

    extern __shared__ __align__(32) char smem_raw[];

    const int tid = threadIdx.x;
    const int wid = tid >> 5;
    const int wm = wid / WARPS_N;
    const int wn = wid % WARPS_N;
    const int row0 = blockIdx.x * BM;

    auto as_hi = [&](int s) { return reinterpret_cast<__nv_bfloat16*>(smem_raw + s * STAGE); };
    auto as_lo = [&](int s) { return reinterpret_cast<__nv_bfloat16*>(smem_raw + s * STAGE + SA); };
    auto bs_hi = [&](int s) { return reinterpret_cast<__nv_bfloat16*>(smem_raw + s * STAGE + 2 * SA); };
    auto bs_lo = [&](int s) { return reinterpret_cast<__nv_bfloat16*>(smem_raw + s * STAGE + 2 * SA + SB); };

    auto copy_stage = [&](int s, int t) {
        const int kbase = t * BK;
#pragma unroll
        for (int idx = tid; idx < BM * (BK / 8); idx += 256) {
            int r = idx / (BK / 8), q = idx % (BK / 8);
            size_t go = (size_t)(row0 + r) * K + kbase + q * 8;
            int so = r * BKP + q * 8;
            __pipeline_memcpy_async(as_hi(s) + so, ga_hi + go, 16);
            __pipeline_memcpy_async(as_lo(s) + so, ga_lo + go, 16);
        }
#pragma unroll
        for (int idx = tid; idx < BK * (BN / 8); idx += 256) {
            int r = idx / (BN / 8), q = idx % (BN / 8);
            size_t go = (size_t)(kbase + r) * N + q * 8;
            int so = r * BNP + q * 8;
            __pipeline_memcpy_async(bs_hi(s) + so, gw2_hi + go, 16);
            __pipeline_memcpy_async(bs_lo(s) + so, gw2_lo + go, 16);
        }
    };

    wmma::fragment<wmma::accumulator, 16, 16, 16, float> acc[AM][AN];
#pragma unroll
    for (int m = 0; m < AM; m++)
#pragma unroll
        for (int n = 0; n < AN; n++) wmma::fill_fragment(acc[m][n], 0.f);

    copy_stage(0, 0);
    __pipeline_commit();

    for (int t = 0; t < T; t++) {
        __pipeline_wait_prior(0);
        __syncthreads();
        if (t + 1 < T) {
            copy_stage((t + 1) & 1, t + 1);
            __pipeline_commit();
        }
        const int s = t & 1;
#pragma unroll
        for (int kk = 0; kk < KK; kk++) {
            wmma::fragment<wmma::matrix_a, 16, 16, 16, __nv_bfloat16, wmma::row_major> ahi[AM], alo[AM];
#pragma unroll
            for (int m = 0; m < AM; m++) {
                int o = (wm * 32 + m * 16) * BKP + kk * 16;
                wmma::load_matrix_sync(ahi[m], as_hi(s) + o, BKP);
                wmma::load_matrix_sync(alo[m], as_lo(s) + o, BKP);
            }
#pragma unroll
            for (int n = 0; n < AN; n++) {
                wmma::fragment<wmma::matrix_b, 16, 16, 16, __nv_bfloat16, wmma::row_major> bhi, blo;
                int o = (kk * 16) * BNP + wn * 32 + n * 16;
                wmma::load_matrix_sync(bhi, bs_hi(s) + o, BNP);
                wmma::load_matrix_sync(blo, bs_lo(s) + o, BNP);
#pragma unroll
                for (int m = 0; m < AM; m++) {
                    wmma::mma_sync(acc[m][n], alo[m], bhi, acc[m][n]);
                    wmma::mma_sync(acc[m][n], ahi[m], blo, acc[m][n]);
                    wmma::mma_sync(acc[m][n], ahi[m], bhi, acc[m][n]);
                }
            }
        }
    }

    // Epilogue: stage f32 tile, convert to fp16, write g_t2h
    __syncthreads();
    float* cst = reinterpret_cast<float*>(smem_raw);   // 128*64*4 = 32KB
#pragma unroll
    for (int m = 0; m < AM; m++)
#pragma unroll
        for (int n = 0; n < AN; n++)
            wmma::store_matrix_sync(cst + (wm * 32 + m * 16) * BN + wn * 32 + n * 16,
                                    acc[m][n], BN, wmma::mem_row_major);
    __syncthreads();
    epilogue_f32_to_h<BM, BN>(cst, g_t2h, row0, tid);
}

// ---------------------------------------------------------------------------
// Launch: fork-join. Chain A (main): wsplit + fused GEMM1.
// Chain B (s2): CSR build. Join before agg1.
// ---------------------------------------------------------------------------
extern "C" void kernel_launch(void* const* d_in, const int* in_sizes, int n_in,
                              void* d_out, int out_size) {
    const float* x   = (const float*)d_in[0];
    const int*   ei  = (const int*)d_in[1];
    const float* W1  = (const float*)d_in[2];
    const float* b1  = (const float*)d_in[3];
    const float* W2  = (const float*)d_in[4];
    const float* b2  = (const float*)d_in[5];
    float*       out = (float*)d_out;

    const int N = in_sizes[0] / IN_F;   // 50000
    const int E = in_sizes[1] / 2;      // 800000
    const int TB = 256;
    const int NB = (N + 255) / 256;

    constexpr int SM1 = 2 * 8192 + 2 * (64 * 48 * 2) + 2 * (2 * 32 * 136 * 2);  // 63488
    constexpr int SM2 = 2 * (2 * 128 * 48 * 2 + 2 * 32 * 80 * 2);               // 69632

    static cudaStream_t s2 = nullptr;
    static cudaEvent_t ev_fork = nullptr, ev_join = nullptr;
    if (s2 == nullptr) {
        cudaStreamCreateWithFlags(&s2, cudaStreamNonBlocking);
        cudaEventCreateWithFlags(&ev_fork, cudaEventDisableTiming);
        cudaEventCreateWithFlags(&ev_join, cudaEventDisableTiming);
        cudaFuncSetAttribute((const void*)gemm1_fused_kernel,
                             cudaFuncAttributeMaxDynamicSharedMemorySize, SM1);
        cudaFuncSetAttribute((const void*)gemm2_kernel,
                             cudaFuncAttributeMaxDynamicSharedMemorySize, SM2);
    }

    // Fork
    cudaEventRecord(ev_fork, 0);
    cudaStreamWaitEvent(s2, ev_fork, 0);

    // Chain B (s2): CSR build (g_cnt is all-zero by invariant)
    detect_kernel<<<1, 32, 0, s2>>>(ei);
    hist_kernel<<<(E + TB - 1) / TB, TB, 0, s2>>>(ei, E);
    scan_local_kernel<<<NB, 256, 0, s2>>>(N);
    scan_bsum_kernel<<<1, 256, 0, s2>>>(NB);
    scan_apply_kernel<<<NB, 256, 0, s2>>>(N);
    scatter_kernel<<<(E + TB - 1) / TB, TB, 0, s2>>>(ei, E);
    cudaEventRecord(ev_join, s2);

    // Chain A (main): weight split + fused GEMM1 (x split inside)
    wsplit_kernel<<<((IN_F * H_F + H_F * OUT_F) / 4 + TB - 1) / TB, TB>>>(W1, W2);
    gemm1_fused_kernel<<<NPAD / 64, 256, SM1>>>(x);

    // Join
    cudaStreamWaitEvent(0, ev_join, 0);

    agg1_kernel<<<(N + 7) / 8, 256>>>(b1, N);
    gemm2_kernel<<<NPAD / 128, 256, SM2>>>();
    agg2_kernel<<<(N + 15) / 16, 256>>>(b2, out, N);
}

// round 17
// speedup vs baseline: 1.2607x; 1.2607x over previous
#include <cuda_runtime.h>
#include <cuda_fp16.h>
#include <cuda_pipeline.h>
#include <mma.h>
#include <cstdint>

using namespace nvcuda;

#define NN     50000
#define NPAD   50048    // = 782*64 = 391*128
#define IN_F   256
#define H_F    128
#define OUT_F  64
#define EMAX   800000

// ---------------------------------------------------------------------------
// Static device scratch
// ---------------------------------------------------------------------------
__device__ __align__(32) float g_t[(size_t)NPAD * H_F];      // GEMM outputs (f32)
__device__ __align__(16) __half ga_h[(size_t)NPAD * H_F];    // hidden acts (fp16)
__device__ __align__(16) __half gw1_h[IN_F * H_F];
__device__ __align__(16) __half gw2_h[H_F * OUT_F];
__device__ float g_dinv[NN];
__device__ int   g_cnt[NN];      // invariant: all-zero at entry of every call
__device__ int   g_off[NN + 1];
__device__ int   g_col[EMAX];
__device__ int   g_bsum[256];
__device__ int   g_is64;

// ---------------------------------------------------------------------------
// Weight convert to fp16 (x convert is fused into GEMM1)
// ---------------------------------------------------------------------------
__global__ void wconv_kernel(const float* __restrict__ W1, const float* __restrict__ W2) {
    int i = blockIdx.x * blockDim.x + threadIdx.x;                 // quad index
    const int Q1 = IN_F * H_F / 4;
    const int Q2 = H_F * OUT_F / 4;
    if (i >= Q1 + Q2) return;
    const float4 v = (i < Q1) ? reinterpret_cast<const float4*>(W1)[i]
                              : reinterpret_cast<const float4*>(W2)[i - Q1];
    __half2 h0 = __floats2half2_rn(v.x, v.y);
    __half2 h1 = __floats2half2_rn(v.z, v.w);
    uint2 packed = make_uint2(*reinterpret_cast<uint32_t*>(&h0),
                              *reinterpret_cast<uint32_t*>(&h1));
    if (i < Q1) reinterpret_cast<uint2*>(gw1_h)[i] = packed;
    else        reinterpret_cast<uint2*>(gw2_h)[i - Q1] = packed;
}

// ---------------------------------------------------------------------------
// Edge width autodetect
// ---------------------------------------------------------------------------
__global__ void detect_kernel(const int* __restrict__ ei32) {
    if (threadIdx.x == 0 && blockIdx.x == 0) {
        int allzero = 1;
        for (int i = 0; i < 64; i++)
            if (ei32[2 * i + 1] != 0) { allzero = 0; break; }
        g_is64 = allzero;
    }
}
__device__ __forceinline__ int edge_src(const int* ei, int E, int e) {
    return g_is64 ? ei[2 * (size_t)e] : ei[(size_t)e];
}
__device__ __forceinline__ int edge_dst(const int* ei, int E, int e) {
    return g_is64 ? ei[2 * ((size_t)E + e)] : ei[(size_t)E + e];
}

// ---------------------------------------------------------------------------
// CSR build. g_cnt is all-zero on entry (restored by scatter's decrement).
// ---------------------------------------------------------------------------
__global__ void hist_kernel(const int* __restrict__ ei, int E) {
    int e = blockIdx.x * blockDim.x + threadIdx.x;
    if (e >= E) return;
    int d = edge_dst(ei, E, e);
    if ((unsigned)d < (unsigned)NN) atomicAdd(&g_cnt[d], 1);
}
__global__ void scan_local_kernel(int n) {
    __shared__ int sh[256];
    const int tid = threadIdx.x;
    const int i = blockIdx.x * 256 + tid;
    int v = (i < n) ? g_cnt[i] : 0;
    sh[tid] = v;
    __syncthreads();
#pragma unroll
    for (int off = 1; off < 256; off <<= 1) {
        int u = (tid >= off) ? sh[tid - off] : 0;
        __syncthreads();
        sh[tid] += u;
        __syncthreads();
    }
    if (i < n) g_off[i] = sh[tid] - v;
    if (tid == 255) g_bsum[blockIdx.x] = sh[255];
}
__global__ void scan_bsum_kernel(int nb) {
    __shared__ int sh[256];
    const int tid = threadIdx.x;
    int v = (tid < nb) ? g_bsum[tid] : 0;
    sh[tid] = v;
    __syncthreads();
#pragma unroll
    for (int off = 1; off < 256; off <<= 1) {
        int u = (tid >= off) ? sh[tid - off] : 0;
        __syncthreads();
        sh[tid] += u;
        __syncthreads();
    }
    if (tid < nb) g_bsum[tid] = sh[tid] - v;
}
__global__ void scan_apply_kernel(int n) {
    int i = blockIdx.x * 256 + threadIdx.x;
    if (i >= n) return;
    int base = g_bsum[blockIdx.x];
    int c = g_cnt[i];                 // NOT reset here; scatter decrements to 0
    int o = g_off[i] + base;
    g_off[i] = o;
    g_dinv[i] = rsqrtf((float)(c + 1));
    if (i == n - 1) g_off[n] = o + c;
}
__global__ void scatter_kernel(const int* __restrict__ ei, int E) {
    int e = blockIdx.x * blockDim.x + threadIdx.x;
    if (e >= E) return;
    int s = edge_src(ei, E, e);
    int d = edge_dst(ei, E, e);
    if ((unsigned)d >= (unsigned)NN) return;
    int r = atomicAdd(&g_cnt[d], -1);            // restores cnt to 0 for next call
    if ((unsigned)s < (unsigned)NN) g_col[g_off[d] + r - 1] = s;
}

// ---------------------------------------------------------------------------
// Aggregation (gather, f32 rows — proven round-15 path).
// agg1: warp per node, edge-unrolled x2; epilogue emits fp16 ga.
// agg2: half-warp (16 lanes x float4) per node, f32 output.
// ---------------------------------------------------------------------------
__global__ void agg1_kernel(const float* __restrict__ b1, int n) {
    int gw   = (blockIdx.x * blockDim.x + threadIdx.x) >> 5;
    int lane = threadIdx.x & 31;
    if (gw >= n) return;
    const float4* __restrict__ trow = reinterpret_cast<const float4*>(g_t);

    float wd = g_dinv[gw];
    float ws = wd * wd;
    float4 v = trow[(size_t)gw * 32 + lane];  // self-loop
    float4 acc = make_float4(v.x * ws, v.y * ws, v.z * ws, v.w * ws);

    int beg = g_off[gw], end = g_off[gw + 1];
    int e = beg;
    for (; e + 1 < end; e += 2) {
        int s0 = g_col[e], s1 = g_col[e + 1];
        float w0 = g_dinv[s0] * wd, w1 = g_dinv[s1] * wd;
        float4 u0 = trow[(size_t)s0 * 32 + lane];
        float4 u1 = trow[(size_t)s1 * 32 + lane];
        acc.x = fmaf(u0.x, w0, acc.x); acc.y = fmaf(u0.y, w0, acc.y);
        acc.z = fmaf(u0.z, w0, acc.z); acc.w = fmaf(u0.w, w0, acc.w);
        acc.x = fmaf(u1.x, w1, acc.x); acc.y = fmaf(u1.y, w1, acc.y);
        acc.z = fmaf(u1.z, w1, acc.z); acc.w = fmaf(u1.w, w1, acc.w);
    }
    if (e < end) {
        int s = g_col[e];
        float w = g_dinv[s] * wd;
        float4 u = trow[(size_t)s * 32 + lane];
        acc.x = fmaf(u.x, w, acc.x); acc.y = fmaf(u.y, w, acc.y);
        acc.z = fmaf(u.z, w, acc.z); acc.w = fmaf(u.w, w, acc.w);
    }
    float4 bb = reinterpret_cast<const float4*>(b1)[lane];
    acc.x = fmaxf(acc.x + bb.x, 0.f);
    acc.y = fmaxf(acc.y + bb.y, 0.f);
    acc.z = fmaxf(acc.z + bb.z, 0.f);
    acc.w = fmaxf(acc.w + bb.w, 0.f);

    __half2 h0 = __floats2half2_rn(acc.x, acc.y);
    __half2 h1 = __floats2half2_rn(acc.z, acc.w);
    uint2 packed = make_uint2(*reinterpret_cast<uint32_t*>(&h0),
                              *reinterpret_cast<uint32_t*>(&h1));
    *reinterpret_cast<uint2*>(ga_h + (size_t)gw * H_F + lane * 4) = packed;
}

__global__ void agg2_kernel(const float* __restrict__ b2, float* __restrict__ out, int n) {
    int gh = (blockIdx.x * blockDim.x + threadIdx.x) >> 4;  // half-warp id = node
    int hl = threadIdx.x & 15;
    if (gh >= n) return;
    const float4* __restrict__ trow = reinterpret_cast<const float4*>(g_t);

    float wd = g_dinv[gh];
    float ws = wd * wd;
    float4 v = trow[(size_t)gh * 16 + hl];
    float4 acc = make_float4(v.x * ws, v.y * ws, v.z * ws, v.w * ws);

    int beg = g_off[gh], end = g_off[gh + 1];
    int e = beg;
    for (; e + 1 < end; e += 2) {
        int s0 = g_col[e], s1 = g_col[e + 1];
        float w0 = g_dinv[s0] * wd, w1 = g_dinv[s1] * wd;
        float4 u0 = trow[(size_t)s0 * 16 + hl];
        float4 u1 = trow[(size_t)s1 * 16 + hl];
        acc.x = fmaf(u0.x, w0, acc.x); acc.y = fmaf(u0.y, w0, acc.y);
        acc.z = fmaf(u0.z, w0, acc.z); acc.w = fmaf(u0.w, w0, acc.w);
        acc.x = fmaf(u1.x, w1, acc.x); acc.y = fmaf(u1.y, w1, acc.y);
        acc.z = fmaf(u1.z, w1, acc.z); acc.w = fmaf(u1.w, w1, acc.w);
    }
    if (e < end) {
        int s = g_col[e];
        float w = g_dinv[s] * wd;
        float4 u = trow[(size_t)s * 16 + hl];
        acc.x = fmaf(u.x, w, acc.x); acc.y = fmaf(u.y, w, acc.y);
        acc.z = fmaf(u.z, w, acc.z); acc.w = fmaf(u.w, w, acc.w);
    }
    float4 bb = reinterpret_cast<const float4*>(b2)[hl];
    acc.x += bb.x; acc.y += bb.y; acc.z += bb.z; acc.w += bb.w;
    reinterpret_cast<float4*>(out)[(size_t)gh * 16 + hl] = acc;
}

// ---------------------------------------------------------------------------
// GEMM1 (fp16 single-pass, FUSED x convert): cp.async raw f32 A tiles,
// convert to fp16 smem; B weights pre-converted fp16. Output f32 -> g_t.
// BM=64, BN=128, BK=32, WM=32, WN=32, K=256. 256 threads.
// smem: A_f32 2x8KB | A_h 6KB | B 2-stage 17.4KB = ~40KB -> high occupancy.
// ---------------------------------------------------------------------------
__global__ void __launch_bounds__(256)
gemm1_fused_kernel(const float* __restrict__ x) {
    constexpr int BM = 64, BN = 128, BK = 32, K = IN_F, N = H_F;
    constexpr int BKP = 48;        // A fp16 row stride (96B)
    constexpr int BNP = 136;       // B fp16 row stride (272B)
    constexpr int T = K / BK;      // 8
    constexpr int KK = BK / 16;    // 2
    constexpr int AM = 2, AN = 2, WARPS_N = 4;
    constexpr int AF_STAGE = BM * BK * 4;            // 8192 B
    constexpr int OFF_AF = 0;                        // 2 stages
    constexpr int OFF_AH = 2 * AF_STAGE;             // 16384
    constexpr int OFF_B  = OFF_AH + BM * BKP * 2;    // +6144 = 22528
    constexpr int SB = BK * BNP * 2;                 // 8704 per stage

    extern __shared__ __align__(32) char smem_raw[];
    float* af = reinterpret_cast<float*>(smem_raw + OFF_AF);
    __half* ah_s = reinterpret_cast<__half*>(smem_raw + OFF_AH);

    const int tid = threadIdx.x;
    const int wid = tid >> 5;
    const int wm = wid / WARPS_N;
    const int wn = wid % WARPS_N;
    const int row0 = blockIdx.x * BM;

    auto bs = [&](int s) { return reinterpret_cast<__half*>(smem_raw + OFF_B + s * SB); };

    auto copy_stage = [&](int s, int t) {
        const int kbase = t * BK;
#pragma unroll
        for (int idx = tid; idx < BM * (BK / 4); idx += 256) {
            int r = idx >> 3, q = idx & 7;
            int gr = row0 + r; if (gr >= NN) gr = NN - 1;   // clamp; zeroed in convert
            __pipeline_memcpy_async(af + s * (AF_STAGE / 4) + idx * 4,
                                    x + (size_t)gr * K + kbase + q * 4, 16);
        }
#pragma unroll
        for (int idx = tid; idx < BK * (BN / 8); idx += 256) {
            int r = idx / (BN / 8), q = idx % (BN / 8);
            __pipeline_memcpy_async(bs(s) + r * BNP + q * 8,
                                    gw1_h + (size_t)(kbase + r) * N + q * 8, 16);
        }
    };

    wmma::fragment<wmma::accumulator, 16, 16, 16, float> acc[AM][AN];
#pragma unroll
    for (int m = 0; m < AM; m++)
#pragma unroll
        for (int n = 0; n < AN; n++) wmma::fill_fragment(acc[m][n], 0.f);

    copy_stage(0, 0);
    __pipeline_commit();

    for (int t = 0; t < T; t++) {
        __pipeline_wait_prior(0);
        __syncthreads();                 // copies done; prior MMAs done
        if (t + 1 < T) {
            copy_stage((t + 1) & 1, t + 1);
            __pipeline_commit();
        }
        const int s = t & 1;
        // Convert A f32 stage -> fp16 buffer
#pragma unroll
        for (int idx = tid; idx < BM * (BK / 4); idx += 256) {
            int r = idx >> 3, c = (idx & 7) * 4;
            float4 v = *reinterpret_cast<const float4*>(af + s * (AF_STAGE / 4) + idx * 4);
            if (row0 + r >= NN) v = make_float4(0.f, 0.f, 0.f, 0.f);
            __half2 h0 = __floats2half2_rn(v.x, v.y);
            __half2 h1 = __floats2half2_rn(v.z, v.w);
            *reinterpret_cast<uint2*>(ah_s + r * BKP + c) =
                make_uint2(*reinterpret_cast<uint32_t*>(&h0),
                           *reinterpret_cast<uint32_t*>(&h1));
        }
        __syncthreads();
#pragma unroll
        for (int kk = 0; kk < KK; kk++) {
            wmma::fragment<wmma::matrix_a, 16, 16, 16, __half, wmma::row_major> a[AM];
#pragma unroll
            for (int m = 0; m < AM; m++)
                wmma::load_matrix_sync(a[m], ah_s + (wm * 32 + m * 16) * BKP + kk * 16, BKP);
#pragma unroll
            for (int n = 0; n < AN; n++) {
                wmma::fragment<wmma::matrix_b, 16, 16, 16, __half, wmma::row_major> b;
                wmma::load_matrix_sync(b, bs(s) + (kk * 16) * BNP + wn * 32 + n * 16, BNP);
#pragma unroll
                for (int m = 0; m < AM; m++)
                    wmma::mma_sync(acc[m][n], a[m], b, acc[m][n]);
            }
        }
    }

#pragma unroll
    for (int m = 0; m < AM; m++)
#pragma unroll
        for (int n = 0; n < AN; n++)
            wmma::store_matrix_sync(g_t + (size_t)(row0 + wm * 32 + m * 16) * N + wn * 32 + n * 16,
                                    acc[m][n], N, wmma::mem_row_major);
}

// ---------------------------------------------------------------------------
// GEMM2 (fp16 single-pass): A = ga_h fp16, B = gw2_h fp16, out f32 -> g_t.
// BM=128, BN=64, BK=32, WM=32, WN=32, K=128, N=64. 256 threads.
// ---------------------------------------------------------------------------
__global__ void __launch_bounds__(256)
gemm2_kernel() {
    constexpr int BM = 128, BN = 64, BK = 32, K = H_F, N = OUT_F;
    constexpr int BKP = 48;
    constexpr int BNP = 80;
    constexpr int WARPS_N = 2;
    constexpr int AM = 2, AN = 2;
    constexpr int KK = 2;
    constexpr int T = K / BK;   // 4
    constexpr int SA = BM * BKP * 2;   // 12288
    constexpr int SB = BK * BNP * 2;   // 5120
    constexpr int STAGE = SA + SB;

    extern __shared__ __align__(32) char smem_raw[];

    const int tid = threadIdx.x;
    const int wid = tid >> 5;
    const int wm = wid / WARPS_N;
    const int wn = wid % WARPS_N;
    const int row0 = blockIdx.x * BM;

    auto as = [&](int s) { return reinterpret_cast<__half*>(smem_raw + s * STAGE); };
    auto bsp = [&](int s) { return reinterpret_cast<__half*>(smem_raw + s * STAGE + SA); };

    auto copy_stage = [&](int s, int t) {
        const int kbase = t * BK;
#pragma unroll
        for (int idx = tid; idx < BM * (BK / 8); idx += 256) {
            int r = idx / (BK / 8), q = idx % (BK / 8);
            __pipeline_memcpy_async(as(s) + r * BKP + q * 8,
                                    ga_h + (size_t)(row0 + r) * K + kbase + q * 8, 16);
        }
#pragma unroll
        for (int idx = tid; idx < BK * (BN / 8); idx += 256) {
            int r = idx / (BN / 8), q = idx % (BN / 8);
            __pipeline_memcpy_async(bsp(s) + r * BNP + q * 8,
                                    gw2_h + (size_t)(kbase + r) * N + q * 8, 16);
        }
    };

    wmma::fragment<wmma::accumulator, 16, 16, 16, float> acc[AM][AN];
#pragma unroll
    for (int m = 0; m < AM; m++)
#pragma unroll
        for (int n = 0; n < AN; n++) wmma::fill_fragment(acc[m][n], 0.f);

    copy_stage(0, 0);
    __pipeline_commit();

    for (int t = 0; t < T; t++) {
        __pipeline_wait_prior(0);
        __syncthreads();
        if (t + 1 < T) {
            copy_stage((t + 1) & 1, t + 1);
            __pipeline_commit();
        }
        const int s = t & 1;
#pragma unroll
        for (int kk = 0; kk < KK; kk++) {
            wmma::fragment<wmma::matrix_a, 16, 16, 16, __half, wmma::row_major> a[AM];
#pragma unroll
            for (int m = 0; m < AM; m++)
                wmma::load_matrix_sync(a[m], as(s) + (wm * 32 + m * 16) * BKP + kk * 16, BKP);
#pragma unroll
            for (int n = 0; n < AN; n++) {
                wmma::fragment<wmma::matrix_b, 16, 16, 16, __half, wmma::row_major> b;
                wmma::load_matrix_sync(b, bsp(s) + (kk * 16) * BNP + wn * 32 + n * 16, BNP);
#pragma unroll
                for (int m = 0; m < AM; m++)
                    wmma::mma_sync(acc[m][n], a[m], b, acc[m][n]);
            }
        }
    }

#pragma unroll
    for (int m = 0; m < AM; m++)
#pragma unroll
        for (int n = 0; n < AN; n++)
            wmma::store_matrix_sync(g_t + (size_t)(row0 + wm * 32 + m * 16) * N + wn * 32 + n * 16,
                                    acc[m][n], N, wmma::mem_row_major);
}

// ---------------------------------------------------------------------------
// Launch: fork-join. Chain A (main): wconv + fused GEMM1.
// Chain B (s2): CSR build. Join before agg1.
// ---------------------------------------------------------------------------
extern "C" void kernel_launch(void* const* d_in, const int* in_sizes, int n_in,
                              void* d_out, int out_size) {
    const float* x   = (const float*)d_in[0];
    const int*   ei  = (const int*)d_in[1];
    const float* W1  = (const float*)d_in[2];
    const float* b1  = (const float*)d_in[3];
    const float* W2  = (const float*)d_in[4];
    const float* b2  = (const float*)d_in[5];
    float*       out = (float*)d_out;

    const int N = in_sizes[0] / IN_F;   // 50000
    const int E = in_sizes[1] / 2;      // 800000
    const int TB = 256;
    const int NB = (N + 255) / 256;

    constexpr int SM1 = 2 * 8192 + 64 * 48 * 2 + 2 * (32 * 136 * 2);  // 39936
    constexpr int SM2 = 2 * (128 * 48 * 2 + 32 * 80 * 2);             // 34816

    static cudaStream_t s2 = nullptr;
    static cudaEvent_t ev_fork = nullptr, ev_join = nullptr;
    if (s2 == nullptr) {
        cudaStreamCreateWithFlags(&s2, cudaStreamNonBlocking);
        cudaEventCreateWithFlags(&ev_fork, cudaEventDisableTiming);
        cudaEventCreateWithFlags(&ev_join, cudaEventDisableTiming);
        cudaFuncSetAttribute((const void*)gemm1_fused_kernel,
                             cudaFuncAttributeMaxDynamicSharedMemorySize, SM1);
        cudaFuncSetAttribute((const void*)gemm2_kernel,
                             cudaFuncAttributeMaxDynamicSharedMemorySize, SM2);
    }

    // Fork
    cudaEventRecord(ev_fork, 0);
    cudaStreamWaitEvent(s2, ev_fork, 0);

    // Chain B (s2): CSR build (g_cnt is all-zero by invariant)
    detect_kernel<<<1, 32, 0, s2>>>(ei);
    hist_kernel<<<(E + TB - 1) / TB, TB, 0, s2>>>(ei, E);
    scan_local_kernel<<<NB, 256, 0, s2>>>(N);
    scan_bsum_kernel<<<1, 256, 0, s2>>>(NB);
    scan_apply_kernel<<<NB, 256, 0, s2>>>(N);
    scatter_kernel<<<(E + TB - 1) / TB, TB, 0, s2>>>(ei, E);
    cudaEventRecord(ev_join, s2);

    // Chain A (main): weight convert + fused GEMM1 (x convert inside)
    wconv_kernel<<<((IN_F * H_F + H_F * OUT_F) / 4 + TB - 1) / TB, TB>>>(W1, W2);
    gemm1_fused_kernel<<<NPAD / 64, 256, SM1>>>(x);

    // Join
    cudaStreamWaitEvent(0, ev_join, 0);

    agg1_kernel<<<(N + 7) / 8, 256>>>(b1, N);
    gemm2_kernel<<<NPAD / 128, 256, SM2>>>();
    agg2_kernel<<<(N + 15) / 16, 256>>>(b2, out, N);
}